// round 3
// baseline (speedup 1.0000x reference)
#include <cuda_runtime.h>

// ---------------------------------------------------------------------------
// Problem constants
// ---------------------------------------------------------------------------
#define B_    512
#define T1_   128
#define IN1_  64
#define H1_   256
#define IN3_  32
#define H3_   128
#define T3_   64
#define P_    12
#define FCIN_ 3872
#define FEATC 3840   // feat buffer excludes the trailing current_game(32)

typedef unsigned long long u64;

// ---------------------------------------------------------------------------
// Device scratch (no allocations allowed — static __device__ arrays)
// ---------------------------------------------------------------------------
__device__ __align__(16) float g_WT1[(IN1_ + H1_) * H1_ * 4];   // [k][j][tau]
__device__ __align__(16) float g_WT2[(IN1_ + H1_) * H1_ * 4];
__device__ __align__(16) float g_WT3[(IN3_ + H3_) * H3_ * 4];
__device__ __align__(16) float g_b1[H1_ * 4];                   // [j][tau] (bih+bhh)
__device__ __align__(16) float g_b2[H1_ * 4];
__device__ __align__(16) float g_b3[H3_ * 4];
__device__ float g_feat[B_ * FEATC];

// ---------------------------------------------------------------------------
// f32x2 helpers — 3-reg FFMA is half-rate on sm_103a (rt_SMSP=2);
// fma.rn.f32x2 restores full 128 MAC/SM/cyc. ptxas won't emit it from C++.
// ---------------------------------------------------------------------------
__device__ __forceinline__ void fma2(u64& acc, u64 a, u64 b) {
    asm("fma.rn.f32x2 %0, %1, %2, %0;" : "+l"(acc) : "l"(a), "l"(b));
}
__device__ __forceinline__ u64 pack2(float x, float y) {
    u64 u; asm("mov.b64 %0, {%1, %2};" : "=l"(u) : "f"(x), "f"(y)); return u;
}
__device__ __forceinline__ float2 unpack2(u64 u) {
    float lo, hi; asm("mov.b64 {%0, %1}, %2;" : "=f"(lo), "=f"(hi) : "l"(u));
    return make_float2(lo, hi);
}
__device__ __forceinline__ float sigf(float x) {
    return __fdividef(1.0f, 1.0f + __expf(-x));
}
__device__ __forceinline__ float tanhfast(float x) {
    // tanh(x) = 2*sigmoid(2x) - 1  (abs err ~1e-6, fine vs 1e-3 tolerance)
    return fmaf(2.0f, sigf(2.0f * x), -1.0f);
}

// ---------------------------------------------------------------------------
// Weight prep: build WT[k][j][tau] = (k<IN ? Wih : Whh)[tau*H+j][...] and
// bias[j][tau] = bih+bhh. Tiny (~3MB writes).
// ---------------------------------------------------------------------------
__global__ void prep_kernel(
    const float* __restrict__ Wih1, const float* __restrict__ Whh1,
    const float* __restrict__ bih1, const float* __restrict__ bhh1,
    const float* __restrict__ Wih2, const float* __restrict__ Whh2,
    const float* __restrict__ bih2, const float* __restrict__ bhh2,
    const float* __restrict__ Wih3, const float* __restrict__ Whh3,
    const float* __restrict__ bih3, const float* __restrict__ bhh3)
{
    int idx = blockIdx.x * blockDim.x + threadIdx.x;
    const int n1 = (IN1_ + H1_) * H1_ * 4;   // 327680
    const int n3 = (IN3_ + H3_) * H3_ * 4;   // 81920

    if (idx < n1) {
        int tau = idx & 3;
        int t2  = idx >> 2;
        int j   = t2 & (H1_ - 1);
        int k   = t2 >> 8;                   // H1_=256
        int g   = tau * H1_ + j;
        g_WT1[idx] = (k < IN1_) ? Wih1[g * IN1_ + k] : Whh1[g * H1_ + (k - IN1_)];
        g_WT2[idx] = (k < IN1_) ? Wih2[g * IN1_ + k] : Whh2[g * H1_ + (k - IN1_)];
    }
    if (idx < n3) {
        int tau = idx & 3;
        int t2  = idx >> 2;
        int j   = t2 & (H3_ - 1);
        int k   = t2 >> 7;                   // H3_=128
        int g   = tau * H3_ + j;
        g_WT3[idx] = (k < IN3_) ? Wih3[g * IN3_ + k] : Whh3[g * H3_ + (k - IN3_)];
    }
    if (idx < H1_ * 4) {
        int tau = idx & 3, j = idx >> 2;
        g_b1[idx] = bih1[tau * H1_ + j] + bhh1[tau * H1_ + j];
        g_b2[idx] = bih2[tau * H1_ + j] + bhh2[tau * H1_ + j];
    }
    if (idx < H3_ * 4) {
        int tau = idx & 3, j = idx >> 2;
        g_b3[idx] = bih3[tau * H3_ + j] + bhh3[tau * H3_ + j];
    }
}

// ---------------------------------------------------------------------------
// Fused LSTM chunk runner.
// Block = 256 threads. Thread grid: TX = H/2 threads over j (2 j's each),
// TY = 256/TX row-groups, RPT = R/TY rows per thread.
// Each thread owns gates for (RPT rows) x (2 j) x (4 gate types) as f32x2
// pairs, plus the matching c-state in registers — the full LSTM cell update
// happens in-register, h is re-shared via smem (stored duplicated {h,h}).
// ---------------------------------------------------------------------------
template<int IN, int H, int TT, int R>
__device__ void run_lstm(const float* __restrict__ WT, const float* __restrict__ bias,
                         const float* const* __restrict__ xrow,
                         float* const* __restrict__ hrow,
                         u64* xh2)
{
    constexpr int K   = IN + H;
    constexpr int TX  = H / 2;
    constexpr int TY  = 256 / TX;
    constexpr int RPT = R / TY;

    const int tid = threadIdx.x;
    const int tx  = tid % TX;       // warp-contiguous in tx -> a-loads broadcast
    const int ty  = tid / TX;
    const int j0  = 2 * tx;
    const int r0  = ty * RPT;

    const ulonglong2* __restrict__ Wv = reinterpret_cast<const ulonglong2*>(WT);
    const ulonglong2* __restrict__ bv = reinterpret_cast<const ulonglong2*>(bias);

    // zero the h region of xh2; c-state in registers
    for (int i = tid; i < H * R; i += 256) xh2[IN * R + i] = 0ull;

    u64   acc[RPT][2][2];
    float c[RPT][2];
#pragma unroll
    for (int rr = 0; rr < RPT; rr++) { c[rr][0] = 0.0f; c[rr][1] = 0.0f; }
    __syncthreads();

    const ulonglong2 bias0 = bv[j0];
    const ulonglong2 bias1 = bv[j0 + 1];

    for (int t = 0; t < TT; t++) {
        // load x_t (coalesced per row), store duplicated {v,v}
        for (int i = tid; i < IN * R; i += 256) {
            int r = i / IN, k = i % IN;
            float v = __ldg(xrow[r] + t * IN + k);
            xh2[k * R + r] = pack2(v, v);
        }
        __syncthreads();

#pragma unroll
        for (int rr = 0; rr < RPT; rr++) {
            acc[rr][0][0] = bias0.x; acc[rr][0][1] = bias0.y;
            acc[rr][1][0] = bias1.x; acc[rr][1][1] = bias1.y;
        }

        const ulonglong2* w  = Wv + j0;   // steps by H per k
        const u64*        xk = xh2 + r0;  // steps by R per k
#pragma unroll 4
        for (int k = 0; k < K; k++) {
            ulonglong2 w0 = w[0];   // j0:   (i,f),(g,o)
            ulonglong2 w1 = w[1];   // j0+1: (i,f),(g,o)
#pragma unroll
            for (int rr = 0; rr < RPT; rr++) {
                u64 a = xk[rr];     // {v,v} broadcast
                fma2(acc[rr][0][0], a, w0.x);
                fma2(acc[rr][0][1], a, w0.y);
                fma2(acc[rr][1][0], a, w1.x);
                fma2(acc[rr][1][1], a, w1.y);
            }
            w += H; xk += R;
        }
        __syncthreads();   // all xh2 reads for step t done before h rewrite

        // cell update (PyTorch gate order i,f,g,o)
#pragma unroll
        for (int rr = 0; rr < RPT; rr++) {
#pragma unroll
            for (int jj = 0; jj < 2; jj++) {
                float2 pif = unpack2(acc[rr][jj][0]);   // (i, f)
                float2 pgo = unpack2(acc[rr][jj][1]);   // (g, o)
                float cn = sigf(pif.y) * c[rr][jj] + sigf(pif.x) * tanhfast(pgo.x);
                float h  = sigf(pgo.y) * tanhfast(cn);
                c[rr][jj] = cn;
                xh2[(IN + j0 + jj) * R + (r0 + rr)] = pack2(h, h);
                if (t == TT - 1) hrow[r0 + rr][j0 + jj] = h;
            }
        }
        // next-iter x-load writes only the x region; h writes are ordered
        // against next GEMM reads by the sync after the x-load.
    }
    __syncthreads();   // chunk boundary: xh2/s_x reuse
}

// ---------------------------------------------------------------------------
// Main fused kernel: 128 blocks, each statically assigned 6 equal work quanta.
//   LSTM1: 128 chunks (R=8, rows 0..1023 = home||away), 2q each
//   LSTM2:  64 chunks (R=8, rows 0..511), 2q each
//   LSTM3: 384 chunks (R=32, rows 0..12287 = home||away players), 1q each
// ---------------------------------------------------------------------------
__global__ __launch_bounds__(256) void lstm_main(
    const float* __restrict__ games_home, const float* __restrict__ games_away,
    const float* __restrict__ games_vs,   const float* __restrict__ players_home,
    const float* __restrict__ players_away)
{
    __shared__ u64 xh2[(IN3_ + H3_) * 32];   // 5120 u64 = 40KB (covers both configs)
    __shared__ const float* s_x[32];
    __shared__ float*       s_h[32];

    const int b   = blockIdx.x;
    const int tid = threadIdx.x;

    int ctype[6], crow[6], nc = 0;
    if (b < 42) {
        for (int i = 0; i < 3; i++) { ctype[nc] = 0; crow[nc++] = (b * 3 + i) * 8; }
    } else if (b == 42) {
        ctype[0] = 0; crow[0] = 1008;
        ctype[1] = 0; crow[1] = 1016;
        ctype[2] = 2; crow[2] = 0;
        ctype[3] = 2; crow[3] = 32;
        nc = 4;
    } else if (b < 75) {
        int q = b - 43;
        ctype[0] = 1; crow[0] = (2 * q) * 8;
        ctype[1] = 1; crow[1] = (2 * q + 1) * 8;
        ctype[2] = 2; crow[2] = (2 + 2 * q) * 32;
        ctype[3] = 2; crow[3] = (3 + 2 * q) * 32;
        nc = 4;
    } else {
        int q = b - 75;
        for (int i = 0; i < 6; i++) { ctype[nc] = 2; crow[nc++] = (66 + 6 * q + i) * 32; }
    }

    for (int ci = 0; ci < nc; ci++) {
        int type = ctype[ci], row0 = crow[ci];
        if (type == 0) {
            if (tid < 8) {
                int gr = row0 + tid;
                s_x[tid] = (gr < 512) ? games_home + gr * (T1_ * IN1_)
                                      : games_away + (gr - 512) * (T1_ * IN1_);
                s_h[tid] = g_feat + (gr & 511) * FEATC + ((gr < 512) ? 0 : 256);
            }
            __syncthreads();
            run_lstm<IN1_, H1_, T1_, 8>(g_WT1, g_b1, s_x, s_h, xh2);
        } else if (type == 1) {
            if (tid < 8) {
                int gr = row0 + tid;
                s_x[tid] = games_vs + gr * (T1_ * IN1_);
                s_h[tid] = g_feat + gr * FEATC + 512;
            }
            __syncthreads();
            run_lstm<IN1_, H1_, T1_, 8>(g_WT2, g_b2, s_x, s_h, xh2);
        } else {
            if (tid < 32) {
                int gr   = row0 + tid;
                bool hm  = (gr < 6144);
                int  g2  = hm ? gr : gr - 6144;
                int  bb  = g2 / 12;
                int  pp  = g2 - 12 * bb;
                s_x[tid] = (hm ? players_home : players_away) + g2 * (T3_ * IN3_);
                s_h[tid] = g_feat + bb * FEATC + (hm ? 768 : 2304) + pp * H3_;
            }
            __syncthreads();
            run_lstm<IN3_, H3_, T3_, 32>(g_WT3, g_b3, s_x, s_h, xh2);
        }
    }
}

// ---------------------------------------------------------------------------
// Final FC: out[b][o] = feat[b] . Wfc[o] + bfc[o]   (current_game read direct)
// ---------------------------------------------------------------------------
__global__ void fc_kernel(const float* __restrict__ cg, const float* __restrict__ Wfc,
                          const float* __restrict__ bfc, float* __restrict__ out)
{
    const int b = blockIdx.x, tid = threadIdx.x;   // 128 threads
    const float* f = g_feat + b * FEATC;
    float a0 = 0.0f, a1 = 0.0f;
    for (int i = tid; i < FEATC; i += 128) {
        float v = f[i];
        a0 = fmaf(v, Wfc[i], a0);
        a1 = fmaf(v, Wfc[FCIN_ + i], a1);
    }
    if (tid < 32) {
        float v = cg[b * 32 + tid];
        a0 = fmaf(v, Wfc[FEATC + tid], a0);
        a1 = fmaf(v, Wfc[FCIN_ + FEATC + tid], a1);
    }
#pragma unroll
    for (int o = 16; o > 0; o >>= 1) {
        a0 += __shfl_down_sync(0xffffffffu, a0, o);
        a1 += __shfl_down_sync(0xffffffffu, a1, o);
    }
    __shared__ float r0[4], r1[4];
    int w = tid >> 5, l = tid & 31;
    if (l == 0) { r0[w] = a0; r1[w] = a1; }
    __syncthreads();
    if (tid == 0) {
        out[b * 2 + 0] = r0[0] + r0[1] + r0[2] + r0[3] + bfc[0];
        out[b * 2 + 1] = r1[0] + r1[1] + r1[2] + r1[3] + bfc[1];
    }
}

// ---------------------------------------------------------------------------
// kernel_launch
// ---------------------------------------------------------------------------
extern "C" void kernel_launch(void* const* d_in, const int* in_sizes, int n_in,
                              void* d_out, int out_size)
{
    (void)in_sizes; (void)n_in; (void)out_size;
    const float* current_game = (const float*)d_in[0];
    const float* games_home   = (const float*)d_in[1];
    const float* games_away   = (const float*)d_in[2];
    const float* games_vs     = (const float*)d_in[3];
    const float* players_home = (const float*)d_in[4];
    const float* players_away = (const float*)d_in[5];
    const float* Wih1 = (const float*)d_in[6];
    const float* Whh1 = (const float*)d_in[7];
    const float* bih1 = (const float*)d_in[8];
    const float* bhh1 = (const float*)d_in[9];
    const float* Wih2 = (const float*)d_in[10];
    const float* Whh2 = (const float*)d_in[11];
    const float* bih2 = (const float*)d_in[12];
    const float* bhh2 = (const float*)d_in[13];
    const float* Wih3 = (const float*)d_in[14];
    const float* Whh3 = (const float*)d_in[15];
    const float* bih3 = (const float*)d_in[16];
    const float* bhh3 = (const float*)d_in[17];
    const float* Wfc  = (const float*)d_in[18];
    const float* bfc  = (const float*)d_in[19];

    prep_kernel<<<1280, 256>>>(Wih1, Whh1, bih1, bhh1,
                               Wih2, Whh2, bih2, bhh2,
                               Wih3, Whh3, bih3, bhh3);
    lstm_main<<<128, 256>>>(games_home, games_away, games_vs,
                            players_home, players_away);
    fc_kernel<<<512, 128>>>(current_game, Wfc, bfc, (float*)d_out);
}